// round 6
// baseline (speedup 1.0000x reference)
#include <cuda_runtime.h>
#include <cstdint>

// Problem constants
#define NCH    24          // B*C = 8*3 channels
#define CHPX   (1 << 20)   // pixels per channel
#define NBINS  256
#define HTHR   512         // hist threads/block (16 warps, required by reduce)
#define HX     12          // hist blocks per unit
#define GX_PIX 40          // gather blocks per pix-unit  (~131KB traffic)
#define GX_F32 64          // gather blocks per fp32-unit (~131KB traffic)

// Scratch (static device globals — no allocation allowed)
__device__ unsigned int g_hist[2 * NCH * NBINS];     // [0..23]=dst, [24..47]=ref
__device__ float        g_table[NCH * NBINS];        // table value already /255
__device__ unsigned char g_pix[(size_t)NCH * CHPX];  // pix cache (used ch only)

// Bug-faithful: reference reads table[b*c]; only these k are ever used.
__host__ __device__ __forceinline__ bool chan_used(int k) {
    return (k <= 8) || (k <= 14 && (k & 1) == 0);
}

__constant__ unsigned char c_used[12]   = {0,1,2,3,4,5,6,7,8,10,12,14};
__constant__ unsigned char c_unused[12] = {9,11,13,15,16,17,18,19,20,21,22,23};

// ---------------------------------------------------------------------------
// K0: zero the global histograms (required every graph replay)
// ---------------------------------------------------------------------------
__global__ void k_zero_hist() {
    int i = blockIdx.x * blockDim.x + threadIdx.x;
    if (i < 2 * NCH * NBINS) g_hist[i] = 0u;
}

// ---------------------------------------------------------------------------
// K1: pair-histogram. blockIdx.y = unit:
//   [0,12):  dst used channel  (hist + pix-byte write)
//   [12,24): ref used channel  (hist only)
// Two pixels -> one smem atomic into a 256x256 byte-counter joint table
// (64KB). 1-D hist = row sums (dp4a) + column sums (coalesced word reads +
// dp4a byte masks). 12M lane-atomics total vs 24M in the scalar scheme.
// Byte overflow impossible here: ~44K pairs/block over 64K pair-bins.
// ---------------------------------------------------------------------------
extern __shared__ unsigned int s_T[];  // 16384 words table + 256 words csum

__global__ __launch_bounds__(HTHR) void k_hist(const float* __restrict__ dst,
                                               const float* __restrict__ ref) {
    unsigned int* T    = s_T;           // 16384 words (256 rows x 64 words)
    unsigned int* csum = s_T + 16384;   // 256 words

    const int u = blockIdx.y;
    const bool is_dst = u < 12;
    const int k = is_dst ? c_used[u] : c_used[u - 12];
    const int hist_slot = is_dst ? k : NCH + k;

    const int tid = threadIdx.x;

    #pragma unroll
    for (int j = tid; j < 16384; j += HTHR) T[j] = 0u;
    if (tid < NBINS) csum[tid] = 0u;
    __syncthreads();

    const float* __restrict__ src = (is_dst ? dst : ref) + (size_t)k * CHPX;
    const float4* __restrict__ s4 = reinterpret_cast<const float4*>(src);
    uchar4* __restrict__ p4 =
        is_dst ? reinterpret_cast<uchar4*>(g_pix) + (size_t)k * (CHPX / 4)
               : nullptr;

    const float scale = 256.0f / 255.0f;  // f32(BINS/255.0)
    const int n4 = CHPX / 4;
    const int stride = HX * HTHR;

    for (int i = blockIdx.x * HTHR + tid; i < n4; i += stride) {
        float4 v = __ldcs(&s4[i]);
        // img255 first (f32), then *scale (f32) — bit-faithful to reference
        float t0 = v.x * 255.0f, t1 = v.y * 255.0f;
        float t2 = v.z * 255.0f, t3 = v.w * 255.0f;
        int i0 = min(max((int)(t0 * scale), 0), 255);
        int i1 = min(max((int)(t1 * scale), 0), 255);
        int i2 = min(max((int)(t2 * scale), 0), 255);
        int i3 = min(max((int)(t3 * scale), 0), 255);
        int idx01 = (i0 << 8) | i1;   // pixel0 -> row, pixel1 -> col
        int idx23 = (i2 << 8) | i3;
        atomicAdd(&T[idx01 >> 2], 1u << ((idx01 & 3) * 8));
        atomicAdd(&T[idx23 >> 2], 1u << ((idx23 & 3) * 8));
        if (is_dst) {
            // pix = clip(trunc(x*255), 0, 255)
            uchar4 p;
            p.x = (unsigned char)min(max((int)t0, 0), 255);
            p.y = (unsigned char)min(max((int)t1, 0), 255);
            p.z = (unsigned char)min(max((int)t2, 0), 255);
            p.w = (unsigned char)min(max((int)t3, 0), 255);
            p4[i] = p;
        }
    }
    __syncthreads();

    // Column sums: 16 warps; warp w covers row-group (w>>1), word-column set
    // ((w&1)*32 + lane). Reads are fully coalesced & conflict-free.
    {
        const int w = tid >> 5, l = tid & 31;
        const int wc = ((w & 1) << 5) | l;     // 0..63
        const int r0 = (w >> 1) * 32;          // row group of 32 rows
        unsigned int a0 = 0, a1 = 0, a2 = 0, a3 = 0;
        #pragma unroll 8
        for (int r = r0; r < r0 + 32; r++) {
            unsigned int word = T[r * 64 + wc];
            a0 = __dp4a(word, 0x00000001u, a0);  // byte0 -> col 4*wc+0
            a1 = __dp4a(word, 0x00000100u, a1);  // byte1
            a2 = __dp4a(word, 0x00010000u, a2);  // byte2
            a3 = __dp4a(word, 0x01000000u, a3);  // byte3
        }
        if (a0) atomicAdd(&csum[4 * wc + 0], a0);
        if (a1) atomicAdd(&csum[4 * wc + 1], a1);
        if (a2) atomicAdd(&csum[4 * wc + 2], a2);
        if (a3) atomicAdd(&csum[4 * wc + 3], a3);
    }
    __syncthreads();

    // Row sums (dp4a over 64 packed words) + merge + global flush
    if (tid < NBINS) {
        unsigned int rs = 0;
        #pragma unroll 16
        for (int j = 0; j < 64; j++)
            rs = __dp4a(T[tid * 64 + j], 0x01010101u, rs);
        unsigned int tot = rs + csum[tid];
        if (tot) atomicAdd(&g_hist[hist_slot * NBINS + tid], tot);
    }
}

// ---------------------------------------------------------------------------
// K2: per-channel CDFs + transfer table (used channels only).
// ---------------------------------------------------------------------------
__global__ void k_table() {
    const int k = blockIdx.x;
    if (!chan_used(k)) return;
    __shared__ float cd[NBINS];
    __shared__ float cr[NBINS];
    const int t = threadIdx.x;  // 256 threads

    // counts sum to exactly 2^20 -> normalization is an exact pow2 multiply
    cd[t] = (float)g_hist[k * NBINS + t] * (1.0f / 1048576.0f);
    cr[t] = (float)g_hist[(NCH + k) * NBINS + t] * (1.0f / 1048576.0f);
    __syncthreads();

    if (t == 0) {  // sequential f32 cumsum, same order as reference
        float a = 0.0f, b = 0.0f;
        for (int i = 0; i < NBINS; i++) {
            a += cd[i]; cd[i] = a;
            b += cr[i]; cr[i] = b;
        }
    }
    __syncthreads();

    int val = t;
    if (t > 0 && t < NBINS - 1) {
        const float x = cd[t];
        #pragma unroll 8
        for (int j = 1; j < NBINS; j++) {
            if (cr[j - 1] <= x && x <= cr[j]) { val = j; break; }
        }
    }
    g_table[k * NBINS + t] = (float)val / 255.0f;
}

// ---------------------------------------------------------------------------
// K3: gather, flat 1-D grid, traffic-balanced blocks.
//   blocks [0, 12*GX_PIX):            used dst channels, read cached pix
//   blocks [12*GX_PIX, +12*GX_F32):   unused dst channels, read fp32 inline
// LUT replicated 4x to cut LDS bank-conflict degree.
// Bug-faithful mapping: channel (b,c) uses table[b*c].
// ---------------------------------------------------------------------------
__global__ __launch_bounds__(256) void k_gather(const float* __restrict__ dst,
                                                float* __restrict__ out) {
    const int bid = blockIdx.x;
    const bool from_pix = bid < 12 * GX_PIX;
    int unit, sub, nsub;
    if (from_pix) { unit = bid / GX_PIX; sub = bid % GX_PIX; nsub = GX_PIX; }
    else {
        int r = bid - 12 * GX_PIX;
        unit = r / GX_F32; sub = r % GX_F32; nsub = GX_F32;
    }
    const int ch = from_pix ? c_used[unit] : c_unused[unit];
    const int b = ch / 3, c = ch % 3;
    const int k = b * c;                // bug-faithful table index

    __shared__ float lut4[NBINS * 4];   // 4-way replicated
    for (int j = threadIdx.x; j < NBINS * 4; j += blockDim.x)
        lut4[j] = g_table[k * NBINS + (j >> 2)];
    __syncthreads();
    const int r4 = threadIdx.x & 3;

    float4* __restrict__ o4 =
        reinterpret_cast<float4*>(out) + (size_t)ch * (CHPX / 4);
    const int n4 = CHPX / 4;
    const int stride = nsub * blockDim.x;

    if (from_pix) {
        const uchar4* __restrict__ p4 =
            reinterpret_cast<const uchar4*>(g_pix) + (size_t)ch * (CHPX / 4);
        for (int i = sub * blockDim.x + threadIdx.x; i < n4; i += stride) {
            uchar4 p = p4[i];
            o4[i] = make_float4(lut4[p.x * 4 + r4], lut4[p.y * 4 + r4],
                                lut4[p.z * 4 + r4], lut4[p.w * 4 + r4]);
        }
    } else {
        const float4* __restrict__ s4 =
            reinterpret_cast<const float4*>(dst) + (size_t)ch * (CHPX / 4);
        for (int i = sub * blockDim.x + threadIdx.x; i < n4; i += stride) {
            float4 v = __ldcs(&s4[i]);
            int i0 = min(max((int)(v.x * 255.0f), 0), 255);
            int i1 = min(max((int)(v.y * 255.0f), 0), 255);
            int i2 = min(max((int)(v.z * 255.0f), 0), 255);
            int i3 = min(max((int)(v.w * 255.0f), 0), 255);
            o4[i] = make_float4(lut4[i0 * 4 + r4], lut4[i1 * 4 + r4],
                                lut4[i2 * 4 + r4], lut4[i3 * 4 + r4]);
        }
    }
}

// ---------------------------------------------------------------------------
extern "C" void kernel_launch(void* const* d_in, const int* in_sizes, int n_in,
                              void* d_out, int out_size) {
    const float* dst = (const float*)d_in[0];
    const float* ref = (const float*)d_in[1];
    float* out = (float*)d_out;

    static const int HSMEM = (16384 + 256) * 4;  // 66KB
    cudaFuncSetAttribute(k_hist, cudaFuncAttributeMaxDynamicSharedMemorySize,
                         HSMEM);

    k_zero_hist<<<(2 * NCH * NBINS + 255) / 256, 256>>>();
    k_hist<<<dim3(HX, 24), HTHR, HSMEM>>>(dst, ref);
    k_table<<<NCH, NBINS>>>();
    k_gather<<<12 * GX_PIX + 12 * GX_F32, 256>>>(dst, out);
}

// round 8
// speedup vs baseline: 1.0384x; 1.0384x over previous
#include <cuda_runtime.h>
#include <cstdint>

// Problem constants
#define NCH    24          // B*C = 8*3 channels
#define CHPX   (1 << 20)   // pixels per channel
#define NBINS  256
#define HTHR   512         // hist threads/block (16 warps, needed by reduce)
#define HX     16          // hist blocks per unit: 2^18 = 8 * (4 * 16*512)

// Scratch (static device globals — no allocation allowed)
__device__ unsigned int g_hist[2 * NCH * NBINS];     // [0..23]=dst, [24..47]=ref
__device__ float        g_table[NCH * NBINS];        // table value already /255
__device__ unsigned char g_pix[(size_t)NCH * CHPX];  // pix cache (used ch only)

// Bug-faithful: reference reads table[b*c]; only these k are ever used.
__host__ __device__ __forceinline__ bool chan_used(int k) {
    return (k <= 8) || (k <= 14 && (k & 1) == 0);
}

__constant__ unsigned char c_used[12]   = {0,1,2,3,4,5,6,7,8,10,12,14};
__constant__ unsigned char c_unused[12] = {9,11,13,15,16,17,18,19,20,21,22,23};

// ---------------------------------------------------------------------------
// K0: zero the global histograms (required every graph replay)
// ---------------------------------------------------------------------------
__global__ void k_zero_hist() {
    int i = blockIdx.x * blockDim.x + threadIdx.x;
    if (i < 2 * NCH * NBINS) g_hist[i] = 0u;
}

// ---------------------------------------------------------------------------
// K1: pair-histogram v3. blockIdx.y = unit:
//   [0,12):  dst used channel  (hist + pix-byte write)
//   [12,24): ref used channel  (hist only)
// Two pixels -> one smem atomic into a 256x256 byte-counter joint table
// (64KB). MLP=4: four independent float4 loads are issued before any atomic.
// Zero-init and row reduction are uint4-vectorized.
// Byte overflow impossible: 2^16 px/block -> 32K pairs over 64K pair-bins.
// ---------------------------------------------------------------------------
extern __shared__ unsigned int s_T[];  // 16384 words table + 256 words csum

__global__ __launch_bounds__(HTHR) void k_hist(const float* __restrict__ dst,
                                               const float* __restrict__ ref) {
    unsigned int* T    = s_T;           // 16384 words (256 rows x 64 words)
    unsigned int* csum = s_T + 16384;   // 256 words

    const int u = blockIdx.y;
    const bool is_dst = u < 12;
    const int k = is_dst ? c_used[u] : c_used[u - 12];
    const int hist_slot = is_dst ? k : NCH + k;

    const int tid = threadIdx.x;

    // Vectorized zero: 4096 uint4 / 512 threads = 8 STS.128 each
    {
        uint4 z = make_uint4(0u, 0u, 0u, 0u);
        uint4* T4 = reinterpret_cast<uint4*>(T);
        #pragma unroll
        for (int j = 0; j < 8; j++) T4[tid + j * HTHR] = z;
    }
    if (tid < NBINS) csum[tid] = 0u;
    __syncthreads();

    const float* __restrict__ src = (is_dst ? dst : ref) + (size_t)k * CHPX;
    const float4* __restrict__ s4 = reinterpret_cast<const float4*>(src);
    uchar4* __restrict__ p4 =
        is_dst ? reinterpret_cast<uchar4*>(g_pix) + (size_t)k * (CHPX / 4)
               : nullptr;

    const float scale = 256.0f / 255.0f;  // f32(BINS/255.0)
    const int tpu = HX * HTHR;            // threads per unit = 8192
    const int base0 = blockIdx.x * HTHR + tid;

    // 8 outer iterations, each with 4 batched (independent) float4 loads.
    #pragma unroll 2
    for (int o = 0; o < 8; o++) {
        const int i0 = o * 4 * tpu + base0;
        float4 v0 = __ldcs(&s4[i0]);
        float4 v1 = __ldcs(&s4[i0 + tpu]);
        float4 v2 = __ldcs(&s4[i0 + 2 * tpu]);
        float4 v3 = __ldcs(&s4[i0 + 3 * tpu]);

        #pragma unroll
        for (int j = 0; j < 4; j++) {
            float4 v = (j == 0) ? v0 : (j == 1) ? v1 : (j == 2) ? v2 : v3;
            // img255 first (f32), then *scale (f32) — bit-faithful to ref
            float t0 = v.x * 255.0f, t1 = v.y * 255.0f;
            float t2 = v.z * 255.0f, t3 = v.w * 255.0f;
            int b0 = min(max((int)(t0 * scale), 0), 255);
            int b1 = min(max((int)(t1 * scale), 0), 255);
            int b2 = min(max((int)(t2 * scale), 0), 255);
            int b3 = min(max((int)(t3 * scale), 0), 255);
            int idx01 = (b0 << 8) | b1;   // pixel0 -> row, pixel1 -> col
            int idx23 = (b2 << 8) | b3;
            atomicAdd(&T[idx01 >> 2], 1u << ((idx01 & 3) * 8));
            atomicAdd(&T[idx23 >> 2], 1u << ((idx23 & 3) * 8));
            if (is_dst) {
                // pix = clip(trunc(x*255), 0, 255)
                uchar4 p;
                p.x = (unsigned char)min(max((int)t0, 0), 255);
                p.y = (unsigned char)min(max((int)t1, 0), 255);
                p.z = (unsigned char)min(max((int)t2, 0), 255);
                p.w = (unsigned char)min(max((int)t3, 0), 255);
                p4[i0 + j * tpu] = p;
            }
        }
    }
    __syncthreads();

    // Column sums: warp w covers row-group (w>>1)*32, word-columns
    // ((w&1)*32 + lane). Coalesced, conflict-free.
    {
        const int w = tid >> 5, l = tid & 31;
        const int wc = ((w & 1) << 5) | l;     // 0..63
        const int r0 = (w >> 1) * 32;          // 32-row group
        unsigned int a0 = 0, a1 = 0, a2 = 0, a3 = 0;
        #pragma unroll 8
        for (int r = r0; r < r0 + 32; r++) {
            unsigned int word = T[r * 64 + wc];
            a0 = __dp4a(word, 0x00000001u, a0);
            a1 = __dp4a(word, 0x00000100u, a1);
            a2 = __dp4a(word, 0x00010000u, a2);
            a3 = __dp4a(word, 0x01000000u, a3);
        }
        if (a0) atomicAdd(&csum[4 * wc + 0], a0);
        if (a1) atomicAdd(&csum[4 * wc + 1], a1);
        if (a2) atomicAdd(&csum[4 * wc + 2], a2);
        if (a3) atomicAdd(&csum[4 * wc + 3], a3);
    }
    __syncthreads();

    // Row sums via uint4 + dp4a, then merge + global flush
    if (tid < NBINS) {
        const uint4* row = reinterpret_cast<const uint4*>(&T[tid * 64]);
        unsigned int rs = 0;
        #pragma unroll
        for (int j = 0; j < 16; j++) {
            uint4 w4 = row[j];
            rs = __dp4a(w4.x, 0x01010101u, rs);
            rs = __dp4a(w4.y, 0x01010101u, rs);
            rs = __dp4a(w4.z, 0x01010101u, rs);
            rs = __dp4a(w4.w, 0x01010101u, rs);
        }
        unsigned int tot = rs + csum[tid];
        if (tot) atomicAdd(&g_hist[hist_slot * NBINS + tid], tot);
    }
}

// ---------------------------------------------------------------------------
// K2: per-channel CDFs + transfer table (used channels only).
// ---------------------------------------------------------------------------
__global__ void k_table() {
    const int k = blockIdx.x;
    if (!chan_used(k)) return;
    __shared__ float cd[NBINS];
    __shared__ float cr[NBINS];
    const int t = threadIdx.x;  // 256 threads

    // counts sum to exactly 2^20 -> normalization is an exact pow2 multiply
    cd[t] = (float)g_hist[k * NBINS + t] * (1.0f / 1048576.0f);
    cr[t] = (float)g_hist[(NCH + k) * NBINS + t] * (1.0f / 1048576.0f);
    __syncthreads();

    if (t == 0) {  // sequential f32 cumsum, same order as reference
        float a = 0.0f, b = 0.0f;
        for (int i = 0; i < NBINS; i++) {
            a += cd[i]; cd[i] = a;
            b += cr[i]; cr[i] = b;
        }
    }
    __syncthreads();

    int val = t;
    if (t > 0 && t < NBINS - 1) {
        const float x = cd[t];
        #pragma unroll 8
        for (int j = 1; j < NBINS; j++) {
            if (cr[j - 1] <= x && x <= cr[j]) { val = j; break; }
        }
    }
    g_table[k * NBINS + t] = (float)val / 255.0f;
}

// ---------------------------------------------------------------------------
// K3: gather (R5 known-good form + streaming stores).
// Bug-faithful mapping: channel (b,c) uses table[b*c].
//   blockIdx.y in [0,12):  used dst channel   -> read cached pix bytes
//   blockIdx.y in [12,24): unused dst channel -> read fp32, index inline
// ---------------------------------------------------------------------------
__global__ __launch_bounds__(256) void k_gather(const float* __restrict__ dst,
                                                float* __restrict__ out) {
    const int u = blockIdx.y;
    const bool from_pix = u < 12;
    const int ch = from_pix ? c_used[u] : c_unused[u - 12];
    const int b = ch / 3, c = ch % 3;
    const int k = b * c;                // bug-faithful table index

    __shared__ float lut[NBINS];
    if (threadIdx.x < NBINS) lut[threadIdx.x] = g_table[k * NBINS + threadIdx.x];
    __syncthreads();

    float4* __restrict__ o4 =
        reinterpret_cast<float4*>(out) + (size_t)ch * (CHPX / 4);
    const int n4 = CHPX / 4;
    const int stride = gridDim.x * blockDim.x;

    if (from_pix) {
        const uchar4* __restrict__ p4 =
            reinterpret_cast<const uchar4*>(g_pix) + (size_t)ch * (CHPX / 4);
        for (int i = blockIdx.x * blockDim.x + threadIdx.x; i < n4; i += stride) {
            uchar4 p = p4[i];
            float4 r = make_float4(lut[p.x], lut[p.y], lut[p.z], lut[p.w]);
            __stcs(&o4[i], r);
        }
    } else {
        const float4* __restrict__ s4 =
            reinterpret_cast<const float4*>(dst) + (size_t)ch * (CHPX / 4);
        for (int i = blockIdx.x * blockDim.x + threadIdx.x; i < n4; i += stride) {
            float4 v = __ldcs(&s4[i]);
            int i0 = min(max((int)(v.x * 255.0f), 0), 255);
            int i1 = min(max((int)(v.y * 255.0f), 0), 255);
            int i2 = min(max((int)(v.z * 255.0f), 0), 255);
            int i3 = min(max((int)(v.w * 255.0f), 0), 255);
            float4 r = make_float4(lut[i0], lut[i1], lut[i2], lut[i3]);
            __stcs(&o4[i], r);
        }
    }
}

// ---------------------------------------------------------------------------
extern "C" void kernel_launch(void* const* d_in, const int* in_sizes, int n_in,
                              void* d_out, int out_size) {
    const float* dst = (const float*)d_in[0];
    const float* ref = (const float*)d_in[1];
    float* out = (float*)d_out;

    static const int HSMEM = (16384 + 256) * 4;  // 66KB + csum
    cudaFuncSetAttribute(k_hist, cudaFuncAttributeMaxDynamicSharedMemorySize,
                         HSMEM);

    k_zero_hist<<<(2 * NCH * NBINS + 255) / 256, 256>>>();
    k_hist<<<dim3(HX, 24), HTHR, HSMEM>>>(dst, ref);
    k_table<<<NCH, NBINS>>>();
    k_gather<<<dim3(64, 24), 256>>>(dst, out);
}